// round 15
// baseline (speedup 1.0000x reference)
#include <cuda_runtime.h>
#include <cuda_pipeline.h>
#include <cstdint>
#include <cstddef>

// ---------------- problem constants (fixed by dataset) ----------------
#define S_      4
#define DIM_    2048
#define NSEQ_   2048
#define B_      4
#define KTOT_   8192          // S*DIM
#define NTOK_   8192          // B*N
#define NW_     24            // 20 alpha cols + 4 beta cols
#define NACC_   25            // 24 dots + sumsq
#define TOKM_   32            // tokens per reduce CTA (2 warps x 16)
#define KC2_    64            // k elements per chunk
#define NCHUNK_ 128           // total chunks over K
#define KPART_  4             // K split across CTAs
#define CPP_    (NCHUNK_ / KPART_)   // 32 chunks per CTA
#define XROW_   68            // padded smem row (words); 68 % 32 == 4 -> conflict-free A loads

// ---------------- device scratch (no allocation allowed) ----------------
__device__ __align__(16) uint32_t g_wt[KTOT_ * NW_];             // 768 KB folded W' (tf32 bits)
__device__ __align__(16) float    g_dots[NTOK_ * KPART_ * 26];   // partial dots per K-part
__device__ __align__(16) float    g_coef[NTOK_ * 16];            // per-token 4x4 mixing matrix

// m16n8k8 tf32 MMA: D(16x8,f32) += A(16x8,tf32) * B(8x8,tf32)
__device__ __forceinline__ void mma_tf32(float d[4],
                                         uint32_t a0, uint32_t a1, uint32_t a2, uint32_t a3,
                                         uint32_t b0, uint32_t b1)
{
    asm volatile(
        "mma.sync.aligned.m16n8k8.row.col.f32.tf32.tf32.f32 "
        "{%0,%1,%2,%3}, {%4,%5,%6,%7}, {%8,%9}, {%0,%1,%2,%3};"
        : "+f"(d[0]), "+f"(d[1]), "+f"(d[2]), "+f"(d[3])
        : "r"(a0), "r"(a1), "r"(a2), "r"(a3), "r"(b0), "r"(b1));
}

// ---------------------------------------------------------------------------
// Kernel 0: fold gamma into the weights, round to tf32, store row-major [k][24].
// ---------------------------------------------------------------------------
__global__ void prep_kernel(const float* __restrict__ gamma,
                            const float* __restrict__ afn,   // (8192, 20)
                            const float* __restrict__ bfn)   // (8192, 4)
{
    int idx = blockIdx.x * blockDim.x + threadIdx.x;
    if (idx >= KTOT_ * NW_) return;
    int k = idx / NW_;
    int j = idx - k * NW_;
    float g = gamma[k] + 1.f;
    float w = (j < 20) ? afn[k * 20 + j] : bfn[k * 4 + (j - 20)];
    uint32_t t;
    asm("cvt.rna.tf32.f32 %0, %1;" : "=r"(t) : "f"(w * g));
    g_wt[idx] = t;
}

// ---------------------------------------------------------------------------
// Kernel 1: tensor-core GEMV partials. Grid = (NTOK_/32) * KPART_ CTAs.
// CTA (tokgrp, part) computes the 24 dots + sumsq of its 32 tokens restricted
// to K-quarter 'part' (32 chunks of 64 k) and writes them to g_dots.
// 2 warps; warp w owns tokens w*16..w*16+15. Triple-buffered cp.async.
// ---------------------------------------------------------------------------
__global__ void __launch_bounds__(64)
reduce_kernel(const float* __restrict__ residuals)
{
    __shared__ __align__(16) uint32_t xs[3][TOKM_][XROW_];  // 26112 B (fp32 bits)
    __shared__ __align__(16) uint32_t wsm[3][KC2_][NW_];    // 18432 B (tf32 bits)
    __shared__ float red[TOKM_][26];

    const int tid  = threadIdx.x;
    const int lane = tid & 31;
    const int warp = tid >> 5;           // 0 or 1
    const int gid  = lane >> 2;          // 0..7
    const int tig  = lane & 3;           // 0..3
    const int part = blockIdx.x & (KPART_ - 1);
    const int tok0 = (blockIdx.x >> 2) * TOKM_;
    const int b    = tok0 >> 11;         // tile never crosses a batch boundary
    const int n0   = tok0 & (NSEQ_ - 1);
    const int c0   = part * CPP_;        // first chunk of this CTA's K-quarter

    // chunk c covers global k in [c*64,(c+1)*64): stream s = c/32, d0 = (c%32)*64
#define STAGE(c_, buf_) do {                                                               \
        const int s_  = (c_) >> 5;                                                         \
        const int d0_ = ((c_) & 31) << 6;                                                  \
        { int tok_ = tid >> 1; int q0_ = (tid & 1) * 8;                                    \
          const float* src_ = residuals +                                                  \
              ((((size_t)(b * S_ + s_)) * NSEQ_ + (size_t)(n0 + tok_)) * DIM_ + d0_ + q0_ * 4); \
          float* dx_ = (float*)&xs[buf_][tok_][q0_ * 4];                                   \
          _Pragma("unroll")                                                                \
          for (int q_ = 0; q_ < 8; q_++)                                                   \
              __pipeline_memcpy_async(dx_ + q_ * 4, src_ + q_ * 4, 16);                    \
        }                                                                                  \
        { const uint32_t* wsrc_ = g_wt + (size_t)(c_) * KC2_ * NW_;                        \
          uint32_t* wdst_ = &wsm[buf_][0][0];                                              \
          _Pragma("unroll")                                                                \
          for (int i_ = tid; i_ < KC2_ * NW_ / 4; i_ += 64)                                \
              __pipeline_memcpy_async(wdst_ + i_ * 4, wsrc_ + i_ * 4, 16);                 \
        }                                                                                  \
    } while (0)

    float d[3][4];
#pragma unroll
    for (int ng = 0; ng < 3; ng++)
#pragma unroll
        for (int r = 0; r < 4; r++) d[ng][r] = 0.f;
    float s0 = 0.f, s1 = 0.f;            // fp32 sumsq for rows gid, gid+8

    const int rowA = warp * 16 + gid;    // this lane's low token row

    STAGE(c0, 0); __pipeline_commit();
    STAGE(c0 + 1, 1); __pipeline_commit();

    for (int i = 0; i < CPP_; i++) {
        __pipeline_wait_prior(1);        // chunk c0+i fully staged
        __syncthreads();                 // visible to all; buffer (i+2)%3 free

        const int buf = i % 3;
#pragma unroll
        for (int kk = 0; kk < 8; kk++) {
            const int k0 = kk * 8;
            uint32_t a0 = xs[buf][rowA][k0 + tig];
            uint32_t a1 = xs[buf][rowA + 8][k0 + tig];
            uint32_t a2 = xs[buf][rowA][k0 + tig + 4];
            uint32_t a3 = xs[buf][rowA + 8][k0 + tig + 4];

            // exact fp32 sumsq from the untruncated x bits
            float f0 = __uint_as_float(a0), f1 = __uint_as_float(a1);
            float f2 = __uint_as_float(a2), f3 = __uint_as_float(a3);
            s0 = fmaf(f0, f0, s0); s0 = fmaf(f2, f2, s0);
            s1 = fmaf(f1, f1, s1); s1 = fmaf(f3, f3, s1);

#pragma unroll
            for (int ng = 0; ng < 3; ng++) {
                uint32_t b0 = wsm[buf][k0 + tig][ng * 8 + gid];
                uint32_t b1 = wsm[buf][k0 + tig + 4][ng * 8 + gid];
                mma_tf32(d[ng], a0, a1, a2, a3, b0, b1);
            }
        }

        if (i + 2 < CPP_) { STAGE(c0 + i + 2, (i + 2) % 3); }
        __pipeline_commit();             // keeps group accounting aligned
    }
#undef STAGE

    // ---- gather partial dots into red[token][0..24] ----
    const int tokA = warp * 16 + gid;
    const int tokB = tokA + 8;
#pragma unroll
    for (int ng = 0; ng < 3; ng++) {
        red[tokA][ng * 8 + tig * 2]     = d[ng][0];
        red[tokA][ng * 8 + tig * 2 + 1] = d[ng][1];
        red[tokB][ng * 8 + tig * 2]     = d[ng][2];
        red[tokB][ng * 8 + tig * 2 + 1] = d[ng][3];
    }
    s0 += __shfl_xor_sync(0xffffffffu, s0, 1);
    s0 += __shfl_xor_sync(0xffffffffu, s0, 2);
    s1 += __shfl_xor_sync(0xffffffffu, s1, 1);
    s1 += __shfl_xor_sync(0xffffffffu, s1, 2);
    if (tig == 0) { red[tokA][24] = s0; red[tokB][24] = s1; }
    __syncthreads();

    // ---- write partials to global ----
    for (int i = tid; i < TOKM_ * NACC_; i += 64) {
        int t = i / NACC_;
        int j = i - t * NACC_;
        g_dots[((size_t)(tok0 + t) * KPART_ + part) * 26 + j] = red[t][j];
    }
}

// ---------------------------------------------------------------------------
// Kernel 2: per-token epilogue. Sum the 4 K-part partials, then
// scale/sigmoid/Sinkhorn(20)/beta -> 4x4 mixing matrix in g_coef.
// ---------------------------------------------------------------------------
__global__ void coef_kernel(const float* __restrict__ sa,   // static_alpha (4,5)
                            const float* __restrict__ pbs,  // pre_branch_scale (1,)
                            const float* __restrict__ rsc,  // residual_scale (1,)
                            const float* __restrict__ sb,   // static_beta (4,)
                            const float* __restrict__ hps)  // h_post_scale scalar
{
    int tok = blockIdx.x * blockDim.x + threadIdx.x;
    if (tok >= NTOK_) return;

    float vv[NACC_];
#pragma unroll
    for (int j = 0; j < NACC_; j++) {
        float sm = 0.f;
#pragma unroll
        for (int p = 0; p < KPART_; p++)
            sm += g_dots[((size_t)tok * KPART_ + p) * 26 + j];
        vv[j] = sm;
    }

    const float scale = 90.50966799187809f / fmaxf(sqrtf(vv[24]), 1e-12f);
    const float pre = pbs[0] * scale;
    const float rs  = rsc[0] * scale;
    const float hp  = hps[0] * scale;

    float P[4], M[4][4];
#pragma unroll
    for (int s = 0; s < 4; s++) {
        P[s] = 1.f / (1.f + __expf(-(vv[s * 5] * pre + sa[s * 5])));
#pragma unroll
        for (int u = 0; u < 4; u++)
            M[s][u] = vv[s * 5 + 1 + u] * rs + sa[s * 5 + 1 + u];
    }

    for (int it = 0; it < 20; it++) {
        // column LSE (over s)
#pragma unroll
        for (int u = 0; u < 4; u++) {
            float m = fmaxf(fmaxf(M[0][u], M[1][u]), fmaxf(M[2][u], M[3][u]));
            float sm = __expf(M[0][u] - m) + __expf(M[1][u] - m)
                     + __expf(M[2][u] - m) + __expf(M[3][u] - m);
            float l = m + __logf(sm);
            M[0][u] -= l; M[1][u] -= l; M[2][u] -= l; M[3][u] -= l;
        }
        // row LSE (over t)
#pragma unroll
        for (int s = 0; s < 4; s++) {
            float m = fmaxf(fmaxf(M[s][0], M[s][1]), fmaxf(M[s][2], M[s][3]));
            float sm = __expf(M[s][0] - m) + __expf(M[s][1] - m)
                     + __expf(M[s][2] - m) + __expf(M[s][3] - m);
            float l = m + __logf(sm);
            M[s][0] -= l; M[s][1] -= l; M[s][2] -= l; M[s][3] -= l;
        }
    }

    float beta[4];
#pragma unroll
    for (int so = 0; so < 4; so++)
        beta[so] = 2.f / (1.f + __expf(-(vv[20 + so] * hp + sb[so])));

#pragma unroll
    for (int so = 0; so < 4; so++)
#pragma unroll
        for (int s = 0; s < 4; s++)
            g_coef[(size_t)tok * 16 + so * 4 + s] = beta[so] * P[s] + __expf(M[s][so]);
}

// ---------------------------------------------------------------------------
// Kernel 3: streaming mix.  out[b*4+so, n, d] = sum_s C[so][s] * r[b*4+s, n, d]
// One CTA per (b, n); 512 threads, one float4 each. Already at DRAM roofline.
// ---------------------------------------------------------------------------
__global__ void __launch_bounds__(512)
mix_kernel(const float* __restrict__ residuals, float* __restrict__ out)
{
    __shared__ float C[16];
    const int blk = blockIdx.x;            // b*2048 + n == token id
    const int b   = blk >> 11;
    const int n   = blk & (NSEQ_ - 1);
    if (threadIdx.x < 16) C[threadIdx.x] = g_coef[(size_t)blk * 16 + threadIdx.x];
    __syncthreads();

    const size_t str  = (size_t)NSEQ_ * (DIM_ / 4);                      // float4 per stream
    const size_t base = ((size_t)(b * S_) * NSEQ_ + n) * (DIM_ / 4) + threadIdx.x;
    const float4* in = (const float4*)residuals;
    float4*       ov = (float4*)out;

    float4 r0 = in[base];
    float4 r1 = in[base + str];
    float4 r2 = in[base + 2 * str];
    float4 r3 = in[base + 3 * str];

#pragma unroll
    for (int so = 0; so < 4; so++) {
        float c0 = C[so * 4 + 0], c1 = C[so * 4 + 1], c2 = C[so * 4 + 2], c3 = C[so * 4 + 3];
        float4 o;
        o.x = c0 * r0.x + c1 * r1.x + c2 * r2.x + c3 * r3.x;
        o.y = c0 * r0.y + c1 * r1.y + c2 * r2.y + c3 * r3.y;
        o.z = c0 * r0.z + c1 * r1.z + c2 * r2.z + c3 * r3.z;
        o.w = c0 * r0.w + c1 * r1.w + c2 * r2.w + c3 * r3.w;
        ov[base + (size_t)so * str] = o;
    }
}

// ---------------------------------------------------------------------------
extern "C" void kernel_launch(void* const* d_in, const int* in_sizes, int n_in,
                              void* d_out, int out_size)
{
    const float* residuals = (const float*)d_in[0];
    const float* gamma     = (const float*)d_in[1];
    const float* afn       = (const float*)d_in[2];
    const float* sa        = (const float*)d_in[3];
    const float* pbs       = (const float*)d_in[4];
    const float* rsc       = (const float*)d_in[5];
    const float* bfn       = (const float*)d_in[6];
    const float* sb        = (const float*)d_in[7];
    const float* hps       = (const float*)d_in[8];
    float* out = (float*)d_out;

    prep_kernel<<<(KTOT_ * NW_ + 255) / 256, 256>>>(gamma, afn, bfn);
    reduce_kernel<<<(NTOK_ / TOKM_) * KPART_, 64>>>(residuals);
    coef_kernel<<<NTOK_ / 256, 256>>>(sa, pbs, rsc, sb, hps);
    mix_kernel<<<B_ * NSEQ_, 512>>>(residuals, out);
}